// round 4
// baseline (speedup 1.0000x reference)
#include <cuda_runtime.h>
#include <cuda_bf16.h>

// ---------------------------------------------------------------------------
// SparseGATv2Layer, edge-sorted + online-softmax, launch-fused.
//   K1 initdetect : zero cnt, probe edge_index dtype (int64 vs int32)
//   K2 gemm+hist  : grid.y=0 proj=x@W_lin^T ; y=1 out=x@W_res^T+bias ;
//                   y=2 histogram of dst (overlaps the GEMM wave)
//   K3 scan       : single-block exclusive scan -> CSR offsets + cursors
//   K4 scatter    : counting-sort edges by dst, payload (src, reduced attr)
//   K5 node       : one warp per dst node, single-pass online softmax,
//                   all state in registers, no atomics.
// ---------------------------------------------------------------------------

#define MAXN 50000
#define MAXE 800000
#define MAXET (MAXE + MAXN)

__device__ float    g_proj[MAXN * 128];     // 25.6 MB
__device__ float2   g_edge_s[MAXET];        // sorted (src bits, reduced attr)
__device__ unsigned g_cnt[MAXN + 4];        // histogram (padded for uint4 loads)
__device__ unsigned g_off[MAXN + 1];        // CSR offsets
__device__ unsigned g_cur[MAXN];            // scatter cursors
__device__ int      g_idx64;

// ---- edge-index accessor: int64 or int32, probed on device --------------------
__device__ __forceinline__ int load_idx(const void* ei, int i) {
    if (g_idx64)
        return (int)((const long long*)ei)[i];
    else
        return ((const int*)ei)[i];
}

// ================================================================================
// K1: zero histogram + dtype probe in one launch
// ================================================================================
__global__ void initdetect_kernel(const long long* ei, int probe, int N) {
    int i = blockIdx.x * blockDim.x + threadIdx.x;
    if (i == 0) { g_idx64 = 1; g_off[0] = 0; g_cur[0] = 0; }
    if (i < N + 4) g_cnt[i] = 0u;
    if (i < probe) {
        long long v = ei[i];
        if (v < 0 || v >= (long long)N) g_idx64 = 0;
    }
}

// ================================================================================
// K2: dual GEMM + histogram.
//  grid.y==0 -> g_proj = x@W_lin^T
//  grid.y==1 -> out    = x@W_res^T + bias
//  grid.y==2 -> histogram of dst over E edges + N self loops
// ================================================================================
__global__ __launch_bounds__(256, 2) void gemm_hist_kernel(
    const float* __restrict__ x, const float* __restrict__ W_lin,
    const float* __restrict__ W_res, const float* __restrict__ bias,
    const void* __restrict__ ei,
    float* __restrict__ out, int N, int E)
{
    if (blockIdx.y == 2) {
        // ---- histogram slice: stride loop over all Et edges ----
        int Et = E + N;
        int stride = gridDim.x * blockDim.x;
        for (int i = blockIdx.x * blockDim.x + threadIdx.x; i < Et; i += stride) {
            int dst = (i < E) ? load_idx(ei, E + i) : (i - E);
            atomicAdd(&g_cnt[dst], 1u);
        }
        return;
    }

    __shared__ float xs[32][132];
    __shared__ float ws[32][132];

    const int tid = threadIdx.x;
    const int tx = tid & 15;
    const int ty = tid >> 4;
    const int rbase = blockIdx.x * 128;
    const float* W = (blockIdx.y == 0) ? W_lin : W_res;

    float acc[8][8];
#pragma unroll
    for (int i = 0; i < 8; i++)
#pragma unroll
        for (int j = 0; j < 8; j++) acc[i][j] = 0.0f;

    for (int kb = 0; kb < 128; kb += 32) {
#pragma unroll
        for (int li = tid; li < 32 * 128; li += 256) {
            int r = li >> 5;
            int k = li & 31;
            int row = rbase + r;
            xs[k][r] = (row < N) ? x[row * 128 + kb + k] : 0.0f;
            ws[k][r] = W[r * 128 + kb + k];
        }
        __syncthreads();
#pragma unroll
        for (int k = 0; k < 32; k++) {
            float a[8], b[8];
            *(float4*)&a[0] = *(const float4*)&xs[k][ty * 8];
            *(float4*)&a[4] = *(const float4*)&xs[k][ty * 8 + 4];
            *(float4*)&b[0] = *(const float4*)&ws[k][tx * 8];
            *(float4*)&b[4] = *(const float4*)&ws[k][tx * 8 + 4];
#pragma unroll
            for (int i = 0; i < 8; i++)
#pragma unroll
                for (int j = 0; j < 8; j++)
                    acc[i][j] = fmaf(a[i], b[j], acc[i][j]);
        }
        __syncthreads();
    }

    const int col = tx * 8;
#pragma unroll
    for (int i = 0; i < 8; i++) {
        int row = rbase + ty * 8 + i;
        if (row >= N) break;
        if (blockIdx.y == 0) {
            *(float4*)&g_proj[row * 128 + col]     = make_float4(acc[i][0], acc[i][1], acc[i][2], acc[i][3]);
            *(float4*)&g_proj[row * 128 + col + 4] = make_float4(acc[i][4], acc[i][5], acc[i][6], acc[i][7]);
        } else {
            float4 v0, v1;
            v0.x = acc[i][0] + bias[col + 0];
            v0.y = acc[i][1] + bias[col + 1];
            v0.z = acc[i][2] + bias[col + 2];
            v0.w = acc[i][3] + bias[col + 3];
            v1.x = acc[i][4] + bias[col + 4];
            v1.y = acc[i][5] + bias[col + 5];
            v1.z = acc[i][6] + bias[col + 6];
            v1.w = acc[i][7] + bias[col + 7];
            *(float4*)&out[row * 128 + col]     = v0;
            *(float4*)&out[row * 128 + col + 4] = v1;
        }
    }
}

// ================================================================================
// K3: single-block exclusive scan, 4 elements per thread, 1024 threads.
// Produces g_off[1..N] (inclusive prefix) and g_cur[1..N-1].
// ================================================================================
__device__ __forceinline__ unsigned warp_incl_scan(unsigned v, int lane) {
#pragma unroll
    for (int d = 1; d < 32; d <<= 1) {
        unsigned t = __shfl_up_sync(0xffffffffu, v, d);
        if (lane >= d) v += t;
    }
    return v;
}

__global__ __launch_bounds__(1024) void scan_kernel(int N) {
    __shared__ unsigned wsum[32];
    __shared__ unsigned s_carry;
    const int tid = threadIdx.x;
    const int lane = tid & 31;
    const int wid = tid >> 5;
    if (tid == 0) s_carry = 0u;
    __syncthreads();

    for (int base = 0; base < N; base += 4096) {
        int i0 = base + tid * 4;
        // g_cnt is padded to N+4 zeros, so a full uint4 load is always safe
        uint4 v = (i0 < N) ? *(const uint4*)&g_cnt[i0] : make_uint4(0u, 0u, 0u, 0u);
        unsigned t = v.x + v.y + v.z + v.w;

        unsigned incl = warp_incl_scan(t, lane);
        if (lane == 31) wsum[wid] = incl;
        __syncthreads();
        if (wid == 0) wsum[lane] = warp_incl_scan(wsum[lane], lane);  // inclusive warp sums
        __syncthreads();

        unsigned carry = s_carry;
        unsigned excl = incl - t + ((wid > 0) ? wsum[wid - 1] : 0u) + carry;

        unsigned p1 = excl + v.x;
        unsigned p2 = p1 + v.y;
        unsigned p3 = p2 + v.z;
        unsigned p4 = p3 + v.w;
        if (i0     < N) { g_off[i0 + 1] = p1; if (i0 + 1 < N) g_cur[i0 + 1] = p1; }
        if (i0 + 1 < N) { g_off[i0 + 2] = p2; if (i0 + 2 < N) g_cur[i0 + 2] = p2; }
        if (i0 + 2 < N) { g_off[i0 + 3] = p3; if (i0 + 3 < N) g_cur[i0 + 3] = p3; }
        if (i0 + 3 < N) { g_off[i0 + 4] = p4; if (i0 + 4 < N) g_cur[i0 + 4] = p4; }

        __syncthreads();                       // everyone done with s_carry + wsum
        if (tid == 0) s_carry = carry + wsum[31];
        __syncthreads();
    }
}

// ================================================================================
// K4: counting-sort scatter, payload = (src bits, reduced edge attr)
// ================================================================================
__global__ void scatter_kernel(const void* __restrict__ ei,
                               const float* __restrict__ ea, int E, int N) {
    int i = blockIdx.x * blockDim.x + threadIdx.x;
    int Et = E + N;
    if (i >= Et) return;
    int src, dst; float red;
    if (i < E) {
        src = load_idx(ei, i);
        dst = load_idx(ei, E + i);
        float2 e2 = ((const float2*)ea)[i];
        red = e2.x + 0.35f * e2.y;
    } else {
        src = dst = i - E;
        red = 1.0f;
    }
    unsigned pos = atomicAdd(&g_cur[dst], 1u);
    g_edge_s[pos] = make_float2(__int_as_float(src), red);
}

// ================================================================================
// K5: GAT node kernel, single pass with online softmax.
// One warp per dst node; lane covers channels 4*lane..4*lane+3, head h=lane>>3.
// ================================================================================
struct EdgeCalc {
    float4 ps;
    float logit;
};

__device__ __forceinline__ EdgeCalc edge_calc(float2 er, const float4* p4,
                                              float4 pd, float4 a4, float web,
                                              int lane)
{
    EdgeCalc r;
    int src = __float_as_int(er.x);
    r.ps = p4[src * 32 + lane];
    float zx = r.ps.x + pd.x; zx = fmaxf(zx, 0.2f * zx);
    float zy = r.ps.y + pd.y; zy = fmaxf(zy, 0.2f * zy);
    float zz = r.ps.z + pd.z; zz = fmaxf(zz, 0.2f * zz);
    float zw = r.ps.w + pd.w; zw = fmaxf(zw, 0.2f * zw);
    float part = zx * a4.x + zy * a4.y + zz * a4.z + zw * a4.w;
    part += __shfl_xor_sync(0xffffffffu, part, 4);
    part += __shfl_xor_sync(0xffffffffu, part, 2);
    part += __shfl_xor_sync(0xffffffffu, part, 1);
    r.logit = fmaf(er.y, web, part);
    return r;
}

__global__ __launch_bounds__(256) void gat_node_kernel(
    const float* __restrict__ att, const float* __restrict__ W_eb,
    float* __restrict__ out, int N)
{
    int warp = (blockIdx.x * blockDim.x + threadIdx.x) >> 5;
    int lane = threadIdx.x & 31;
    if (warp >= N) return;
    const int d = warp;
    const int h = lane >> 3;

    const int beg = (int)g_off[d];
    const int end = (int)g_off[d + 1];

    const float4* p4 = (const float4*)g_proj;
    float4 pd = p4[d * 32 + lane];
    float4 a4 = ((const float4*)att)[lane];
    float web = __ldg(&W_eb[h]);

    float m = -3.4e38f, den = 0.0f;
    float ax = 0.0f, ay = 0.0f, az = 0.0f, aw = 0.0f;

    int j = beg;
    for (; j + 1 < end; j += 2) {
        float2 er0 = g_edge_s[j];
        float2 er1 = g_edge_s[j + 1];
        EdgeCalc c0 = edge_calc(er0, p4, pd, a4, web, lane);
        EdgeCalc c1 = edge_calc(er1, p4, pd, a4, web, lane);

        float mnew = fmaxf(m, fmaxf(c0.logit, c1.logit));
        float s  = __expf(m - mnew);
        float p0 = __expf(c0.logit - mnew);
        float p1 = __expf(c1.logit - mnew);
        den = fmaf(den, s, p0 + p1);
        ax = fmaf(ax, s, fmaf(p0, c0.ps.x, p1 * c1.ps.x));
        ay = fmaf(ay, s, fmaf(p0, c0.ps.y, p1 * c1.ps.y));
        az = fmaf(az, s, fmaf(p0, c0.ps.z, p1 * c1.ps.z));
        aw = fmaf(aw, s, fmaf(p0, c0.ps.w, p1 * c1.ps.w));
        m = mnew;
    }
    if (j < end) {
        float2 er0 = g_edge_s[j];
        EdgeCalc c0 = edge_calc(er0, p4, pd, a4, web, lane);
        float mnew = fmaxf(m, c0.logit);
        float s = __expf(m - mnew);
        float p0 = __expf(c0.logit - mnew);
        den = fmaf(den, s, p0);
        ax = fmaf(ax, s, p0 * c0.ps.x);
        ay = fmaf(ay, s, p0 * c0.ps.y);
        az = fmaf(az, s, p0 * c0.ps.z);
        aw = fmaf(aw, s, p0 * c0.ps.w);
        m = mnew;
    }

    float inv = 1.0f / fmaxf(den, 1e-12f);
    float4* o4 = (float4*)out;
    float4 r = o4[d * 32 + lane];   // residual + bias from GEMM2
    r.x = fmaf(ax, inv, r.x);
    r.y = fmaf(ay, inv, r.y);
    r.z = fmaf(az, inv, r.z);
    r.w = fmaf(aw, inv, r.w);
    o4[d * 32 + lane] = r;
}

// ================================================================================
extern "C" void kernel_launch(void* const* d_in, const int* in_sizes, int n_in,
                              void* d_out, int out_size)
{
    const float* x     = (const float*)d_in[0];
    const void*  ei    = (const void*)d_in[1];
    const float* ea    = (const float*)d_in[2];
    const float* W_lin = (const float*)d_in[3];
    const float* att   = (const float*)d_in[4];
    const float* W_eb  = (const float*)d_in[5];
    const float* bias  = (const float*)d_in[6];
    const float* W_res = (const float*)d_in[7];
    float* out = (float*)d_out;

    int N  = in_sizes[0] / 128;
    int E  = in_sizes[1] / 2;
    int Et = E + N;

    int probe = (E < 65536) ? E : 65536;
    int initThreads = (N + 4 > probe) ? (N + 4) : probe;
    initdetect_kernel<<<(initThreads + 255) / 256, 256>>>((const long long*)ei, probe, N);

    gemm_hist_kernel<<<dim3((N + 127) / 128, 3), 256>>>(x, W_lin, W_res, bias, ei, out, N, E);

    scan_kernel<<<1, 1024>>>(N);

    scatter_kernel<<<(Et + 255) / 256, 256>>>(ei, ea, E, N);

    gat_node_kernel<<<(N * 32 + 255) / 256, 256>>>(att, W_eb, out, N);
}

// round 6
// speedup vs baseline: 1.4708x; 1.4708x over previous
#include <cuda_runtime.h>
#include <cuda_bf16.h>
#include <cstdint>

// ---------------------------------------------------------------------------
// SparseGATv2Layer: HMMA split-bf16 GEMM + edge-sorted online-softmax GAT.
//   K1 initdetect : zero hist, probe edge_index dtype
//   K2 prep       : split x, [W_lin;W_res] into bf16 (hi, lo)
//   K3 hist       : histogram of dst
//   K4-6 scan     : 3-kernel warp-shuffle exclusive scan -> CSR offsets
//   K7 scatter    : counting-sort edges by dst
//   K8 mma_gemm   : mma.sync m16n8k16 bf16, D = Ah*Bh + Al*Bh + Ah*Bl (fp32 acc)
//   K9 node       : one warp per dst node, single-pass online softmax
// ---------------------------------------------------------------------------

#define MAXN 50000
#define MAXE 800000
#define MAXET (MAXE + MAXN)

__device__ float    g_proj[MAXN * 128];
__device__ float2   g_edge_s[MAXET];
__device__ unsigned g_cnt[MAXN + 4];
__device__ unsigned g_tmp[MAXN];
__device__ unsigned g_bsum[1024];
__device__ unsigned g_off[MAXN + 1];
__device__ unsigned g_cur[MAXN];
__device__ int      g_idx64;

__device__ __align__(16) __nv_bfloat16 g_xh[MAXN * 128];
__device__ __align__(16) __nv_bfloat16 g_xl[MAXN * 128];
__device__ __align__(16) __nv_bfloat16 g_wh[256 * 128];
__device__ __align__(16) __nv_bfloat16 g_wl[256 * 128];

__device__ __forceinline__ uint32_t smem_to_u32(const void* p) {
    uint32_t a;
    asm("{ .reg .u64 t; cvta.to.shared.u64 t, %1; cvt.u32.u64 %0, t; }"
        : "=r"(a) : "l"(p));
    return a;
}

#define SWZ128(o) ((o) ^ (((o) >> 3) & 0x70))

#define LDSM_X4(r0, r1, r2, r3, addr) \
    asm volatile("ldmatrix.sync.aligned.m8n8.x4.shared.b16 {%0,%1,%2,%3}, [%4];" \
                 : "=r"(r0), "=r"(r1), "=r"(r2), "=r"(r3) : "r"(addr))

#define MMA16816(c, a, b) \
    asm volatile("mma.sync.aligned.m16n8k16.row.col.f32.bf16.bf16.f32 " \
                 "{%0,%1,%2,%3}, {%4,%5,%6,%7}, {%8,%9}, {%0,%1,%2,%3};" \
                 : "+f"((c)[0]), "+f"((c)[1]), "+f"((c)[2]), "+f"((c)[3]) \
                 : "r"((a)[0]), "r"((a)[1]), "r"((a)[2]), "r"((a)[3]), \
                   "r"((b)[0]), "r"((b)[1]))

// ---- edge-index accessor: int64 or int32, probed on device --------------------
__device__ __forceinline__ int load_idx(const void* ei, int i) {
    if (g_idx64)
        return (int)((const long long*)ei)[i];
    else
        return ((const int*)ei)[i];
}

// ================================================================================
// K1: zero histogram + dtype probe
// ================================================================================
__global__ void initdetect_kernel(const long long* ei, int probe, int N) {
    int i = blockIdx.x * blockDim.x + threadIdx.x;
    if (i == 0) { g_idx64 = 1; g_off[0] = 0; g_cur[0] = 0; }
    if (i < N + 4) g_cnt[i] = 0u;
    if (i < probe) {
        long long v = ei[i];
        if (v < 0 || v >= (long long)N) g_idx64 = 0;
    }
}

// ================================================================================
// K2: bf16 hi/lo split of x and concatenated weights [W_lin ; W_res]
// ================================================================================
__global__ void prep_kernel(const float* __restrict__ x,
                            const float* __restrict__ W_lin,
                            const float* __restrict__ W_res, int n) {
    int i = blockIdx.x * blockDim.x + threadIdx.x;
    int i4 = i * 4;
    if (i4 < n) {
        float4 v = *(const float4*)&x[i4];
        __nv_bfloat16 hx = __float2bfloat16(v.x), hy = __float2bfloat16(v.y);
        __nv_bfloat16 hz = __float2bfloat16(v.z), hw = __float2bfloat16(v.w);
        __nv_bfloat162 h01; h01.x = hx; h01.y = hy;
        __nv_bfloat162 h23; h23.x = hz; h23.y = hw;
        ((__nv_bfloat162*)g_xh)[i * 2]     = h01;
        ((__nv_bfloat162*)g_xh)[i * 2 + 1] = h23;
        __nv_bfloat162 l01, l23;
        l01.x = __float2bfloat16(v.x - __bfloat162float(hx));
        l01.y = __float2bfloat16(v.y - __bfloat162float(hy));
        l23.x = __float2bfloat16(v.z - __bfloat162float(hz));
        l23.y = __float2bfloat16(v.w - __bfloat162float(hw));
        ((__nv_bfloat162*)g_xl)[i * 2]     = l01;
        ((__nv_bfloat162*)g_xl)[i * 2 + 1] = l23;
    }
    if (i < 8192) {
        int j4 = i * 4;
        const float* Wsrc = (j4 < 16384) ? &W_lin[j4] : &W_res[j4 - 16384];
        float4 w = *(const float4*)Wsrc;
        __nv_bfloat16 hx = __float2bfloat16(w.x), hy = __float2bfloat16(w.y);
        __nv_bfloat16 hz = __float2bfloat16(w.z), hw = __float2bfloat16(w.w);
        __nv_bfloat162 h01; h01.x = hx; h01.y = hy;
        __nv_bfloat162 h23; h23.x = hz; h23.y = hw;
        ((__nv_bfloat162*)g_wh)[i * 2]     = h01;
        ((__nv_bfloat162*)g_wh)[i * 2 + 1] = h23;
        __nv_bfloat162 l01, l23;
        l01.x = __float2bfloat16(w.x - __bfloat162float(hx));
        l01.y = __float2bfloat16(w.y - __bfloat162float(hy));
        l23.x = __float2bfloat16(w.z - __bfloat162float(hz));
        l23.y = __float2bfloat16(w.w - __bfloat162float(hw));
        ((__nv_bfloat162*)g_wl)[i * 2]     = l01;
        ((__nv_bfloat162*)g_wl)[i * 2 + 1] = l23;
    }
}

// ================================================================================
// K3: histogram of dst
// ================================================================================
__global__ void hist_kernel(const void* __restrict__ ei, int E, int N) {
    int i = blockIdx.x * blockDim.x + threadIdx.x;
    int Et = E + N;
    if (i >= Et) return;
    int dst = (i < E) ? load_idx(ei, E + i) : (i - E);
    atomicAdd(&g_cnt[dst], 1u);
}

// ---- 3-kernel warp-shuffle scan ------------------------------------------------
__device__ __forceinline__ unsigned warp_incl_scan(unsigned v, int lane) {
#pragma unroll
    for (int d = 1; d < 32; d <<= 1) {
        unsigned t = __shfl_up_sync(0xffffffffu, v, d);
        if (lane >= d) v += t;
    }
    return v;
}

__global__ void scan1_kernel(int N) {
    __shared__ unsigned wsum[32];
    int i = blockIdx.x * 1024 + threadIdx.x;
    int lane = threadIdx.x & 31;
    int wid = threadIdx.x >> 5;
    unsigned v = (i < N) ? g_cnt[i] : 0u;
    unsigned incl = warp_incl_scan(v, lane);
    if (lane == 31) wsum[wid] = incl;
    __syncthreads();
    if (wid == 0) {
        unsigned w = wsum[lane];
        wsum[lane] = warp_incl_scan(w, lane) - w;
    }
    __syncthreads();
    incl += wsum[wid];
    if (i < N) g_tmp[i] = incl;
    if (threadIdx.x == 1023) g_bsum[blockIdx.x] = incl;
}

__global__ void scan2_kernel(int nb) {
    __shared__ unsigned wsum[32];
    int lane = threadIdx.x & 31;
    int wid = threadIdx.x >> 5;
    unsigned v = (threadIdx.x < nb) ? g_bsum[threadIdx.x] : 0u;
    unsigned incl = warp_incl_scan(v, lane);
    if (lane == 31) wsum[wid] = incl;
    __syncthreads();
    if (wid == 0) {
        unsigned w = wsum[lane];
        wsum[lane] = warp_incl_scan(w, lane) - w;
    }
    __syncthreads();
    incl += wsum[wid];
    if (threadIdx.x < nb) g_bsum[threadIdx.x] = incl - v;
}

__global__ void scan3_kernel(int N) {
    int i = blockIdx.x * 1024 + threadIdx.x;
    if (i >= N) return;
    unsigned incl = g_tmp[i] + g_bsum[blockIdx.x];
    g_off[i + 1] = incl;
    if (i + 1 < N) g_cur[i + 1] = incl;
}

// ================================================================================
// K7: counting-sort scatter
// ================================================================================
__global__ void scatter_kernel(const void* __restrict__ ei,
                               const float* __restrict__ ea, int E, int N) {
    int i = blockIdx.x * blockDim.x + threadIdx.x;
    int Et = E + N;
    if (i >= Et) return;
    int src, dst; float red;
    if (i < E) {
        src = load_idx(ei, i);
        dst = load_idx(ei, E + i);
        float2 e2 = ((const float2*)ea)[i];
        red = e2.x + 0.35f * e2.y;
    } else {
        src = dst = i - E;
        red = 1.0f;
    }
    unsigned pos = atomicAdd(&g_cur[dst], 1u);
    g_edge_s[pos] = make_float2(__int_as_float(src), red);
}

// ================================================================================
// K8: HMMA split-bf16 GEMM. CTA = 128 rows x 128 cols; grid.y picks W half.
// D = Ah*Bh + Al*Bh + Ah*Bl, fp32 accumulate, K=128 (2 SMEM blocks of 64).
// SMEM: A hi/lo + B hi/lo, each 2 blocks of (128 rows x 128B, SW128) = 128 KB.
// 8 warps (4 M-groups x 2 N-groups), warp tile 32x64, mma.m16n8k16.
// ================================================================================
#define SA_HI 0
#define SA_LO 32768
#define SB_HI 65536
#define SB_LO 98304
#define GSM_TOTAL 131072

__global__ __launch_bounds__(256, 1) void mma_gemm_kernel(
    const float* __restrict__ bias, float* __restrict__ out, int N)
{
    extern __shared__ char smem[];
    const uint32_t sbase = smem_to_u32(smem);
    const int tid = threadIdx.x;
    const int lane = tid & 31;
    const int wid = tid >> 5;
    const int warpm = wid & 3;        // 4 M-groups of 32 rows
    const int warpn = wid >> 2;       // 2 N-groups of 64 cols
    const int rbase = blockIdx.x * 128;
    const int ybase = blockIdx.y * 128;   // weight-row (output col) base

    // ---- stage A (hi/lo) and B (hi/lo), K split into 2 blocks of 64 cols ----
    const uint4* xh4 = (const uint4*)g_xh;
    const uint4* xl4 = (const uint4*)g_xl;
    const uint4* wh4 = (const uint4*)g_wh;
    const uint4* wl4 = (const uint4*)g_wl;
    const uint4 zero4 = make_uint4(0u, 0u, 0u, 0u);

#pragma unroll
    for (int idx = tid; idx < 128 * 16; idx += 256) {
        int r = idx >> 4;            // row 0..127
        int u = idx & 15;            // uint4 index within 256B row
        int b = u >> 3;              // k-block
        int u8 = u & 7;
        uint32_t off = (uint32_t)(b * 16384) + SWZ128((uint32_t)(r * 128 + u8 * 16));
        int arow = rbase + r;
        int agi = arow * 16 + u;     // uint4 index into [row][128bf16]
        bool ok = (arow < N);
        *(uint4*)(smem + SA_HI + off) = ok ? xh4[agi] : zero4;
        *(uint4*)(smem + SA_LO + off) = ok ? xl4[agi] : zero4;
        int wgi = (ybase + r) * 16 + u;
        *(uint4*)(smem + SB_HI + off) = wh4[wgi];
        *(uint4*)(smem + SB_LO + off) = wl4[wgi];
    }
    __syncthreads();

    float acc[2][8][4];
#pragma unroll
    for (int mt = 0; mt < 2; mt++)
#pragma unroll
        for (int nt = 0; nt < 8; nt++)
#pragma unroll
            for (int q = 0; q < 4; q++) acc[mt][nt][q] = 0.0f;

    // per-thread ldmatrix address components
    // A: lanes 0-7 rows m0..m0+7 seg0 | 8-15 rows +8 seg0 | 16-23 rows m0.. seg1 | 24-31 rows +8 seg1
    const int a_row_off = lane & 15;
    const int a_seg = (lane >> 4) & 1;
    // B: lanes 0-7 rows n0..7 seg0 | 8-15 rows n0..7 seg1 | 16-23 rows n0+8..15 seg0 | 24-31 +8 seg1
    const int b_row_off = (lane & 7) + ((lane >> 4) & 1) * 8;
    const int b_seg = (lane >> 3) & 1;

#pragma unroll
    for (int b = 0; b < 2; b++) {
        const uint32_t ahb = sbase + SA_HI + b * 16384;
        const uint32_t alb = sbase + SA_LO + b * 16384;
        const uint32_t bhb = sbase + SB_HI + b * 16384;
        const uint32_t blb = sbase + SB_LO + b * 16384;
#pragma unroll
        for (int s = 0; s < 4; s++) {
            const int c0 = s * 16;   // bf16 col within 64-col block
            // ---- A fragments (hi, lo): 2 M16 tiles ----
            uint32_t ah[8], al[8];
#pragma unroll
            for (int mt = 0; mt < 2; mt++) {
                int row = warpm * 32 + mt * 16 + a_row_off;
                uint32_t off = SWZ128((uint32_t)(row * 128 + (c0 + a_seg * 8) * 2));
                LDSM_X4(ah[mt*4], ah[mt*4+1], ah[mt*4+2], ah[mt*4+3], ahb + off);
                LDSM_X4(al[mt*4], al[mt*4+1], al[mt*4+2], al[mt*4+3], alb + off);
            }
            // ---- B hi fragments: 4 pairs of n8 tiles ----
            uint32_t bf[16];
#pragma unroll
            for (int p = 0; p < 4; p++) {
                int row = warpn * 64 + p * 16 + b_row_off;
                uint32_t off = SWZ128((uint32_t)(row * 128 + (c0 + b_seg * 8) * 2));
                LDSM_X4(bf[p*4], bf[p*4+1], bf[p*4+2], bf[p*4+3], bhb + off);
            }
#pragma unroll
            for (int mt = 0; mt < 2; mt++)
#pragma unroll
                for (int nt = 0; nt < 8; nt++) {
                    uint32_t* bb = &bf[(nt >> 1) * 4 + (nt & 1) * 2];
                    MMA16816(acc[mt][nt], &ah[mt*4], bb);   // hh
                    MMA16816(acc[mt][nt], &al[mt*4], bb);   // lh
                }
            // ---- B lo fragments reuse bf ----
#pragma unroll
            for (int p = 0; p < 4; p++) {
                int row = warpn * 64 + p * 16 + b_row_off;
                uint32_t off = SWZ128((uint32_t)(row * 128 + (c0 + b_seg * 8) * 2));
                LDSM_X4(bf[p*4], bf[p*4+1], bf[p*4+2], bf[p*4+3], blb + off);
            }
#pragma unroll
            for (int mt = 0; mt < 2; mt++)
#pragma unroll
                for (int nt = 0; nt < 8; nt++) {
                    uint32_t* bb = &bf[(nt >> 1) * 4 + (nt & 1) * 2];
                    MMA16816(acc[mt][nt], &ah[mt*4], bb);   // hl
                }
        }
    }

    // ---- epilogue ----
    // acc[mt][nt]: c0,c1 -> row lane/4,     cols 2*(lane%4)+{0,1}
    //              c2,c3 -> row lane/4 + 8, same cols
    const int rr = lane >> 2;
    const int cc = (lane & 3) * 2;
#pragma unroll
    for (int mt = 0; mt < 2; mt++) {
        int row0 = rbase + warpm * 32 + mt * 16 + rr;
#pragma unroll
        for (int nt = 0; nt < 8; nt++) {
            int col = warpn * 64 + nt * 8 + cc;
            if (blockIdx.y == 0) {
                if (row0 < N)
                    *(float2*)&g_proj[row0 * 128 + col] =
                        make_float2(acc[mt][nt][0], acc[mt][nt][1]);
                if (row0 + 8 < N)
                    *(float2*)&g_proj[(row0 + 8) * 128 + col] =
                        make_float2(acc[mt][nt][2], acc[mt][nt][3]);
            } else {
                float2 bb = *(const float2*)&bias[col];
                if (row0 < N)
                    *(float2*)&out[row0 * 128 + col] =
                        make_float2(acc[mt][nt][0] + bb.x, acc[mt][nt][1] + bb.y);
                if (row0 + 8 < N)
                    *(float2*)&out[(row0 + 8) * 128 + col] =
                        make_float2(acc[mt][nt][2] + bb.x, acc[mt][nt][3] + bb.y);
            }
        }
    }
}

// ================================================================================
// K9: GAT node kernel, single pass with online softmax (unchanged from R3)
// ================================================================================
struct EdgeCalc { float4 ps; float logit; };

__device__ __forceinline__ EdgeCalc edge_calc(float2 er, const float4* p4,
                                              float4 pd, float4 a4, float web,
                                              int lane)
{
    EdgeCalc r;
    int src = __float_as_int(er.x);
    r.ps = p4[src * 32 + lane];
    float zx = r.ps.x + pd.x; zx = fmaxf(zx, 0.2f * zx);
    float zy = r.ps.y + pd.y; zy = fmaxf(zy, 0.2f * zy);
    float zz = r.ps.z + pd.z; zz = fmaxf(zz, 0.2f * zz);
    float zw = r.ps.w + pd.w; zw = fmaxf(zw, 0.2f * zw);
    float part = zx * a4.x + zy * a4.y + zz * a4.z + zw * a4.w;
    part += __shfl_xor_sync(0xffffffffu, part, 4);
    part += __shfl_xor_sync(0xffffffffu, part, 2);
    part += __shfl_xor_sync(0xffffffffu, part, 1);
    r.logit = fmaf(er.y, web, part);
    return r;
}

__global__ __launch_bounds__(256) void gat_node_kernel(
    const float* __restrict__ att, const float* __restrict__ W_eb,
    float* __restrict__ out, int N)
{
    int warp = (blockIdx.x * blockDim.x + threadIdx.x) >> 5;
    int lane = threadIdx.x & 31;
    if (warp >= N) return;
    const int d = warp;
    const int h = lane >> 3;

    const int beg = (int)g_off[d];
    const int end = (int)g_off[d + 1];

    const float4* p4 = (const float4*)g_proj;
    float4 pd = p4[d * 32 + lane];
    float4 a4 = ((const float4*)att)[lane];
    float web = __ldg(&W_eb[h]);

    float m = -3.4e38f, den = 0.0f;
    float ax = 0.0f, ay = 0.0f, az = 0.0f, aw = 0.0f;

    int j = beg;
    for (; j + 1 < end; j += 2) {
        float2 er0 = g_edge_s[j];
        float2 er1 = g_edge_s[j + 1];
        EdgeCalc c0 = edge_calc(er0, p4, pd, a4, web, lane);
        EdgeCalc c1 = edge_calc(er1, p4, pd, a4, web, lane);

        float mnew = fmaxf(m, fmaxf(c0.logit, c1.logit));
        float s  = __expf(m - mnew);
        float p0 = __expf(c0.logit - mnew);
        float p1 = __expf(c1.logit - mnew);
        den = fmaf(den, s, p0 + p1);
        ax = fmaf(ax, s, fmaf(p0, c0.ps.x, p1 * c1.ps.x));
        ay = fmaf(ay, s, fmaf(p0, c0.ps.y, p1 * c1.ps.y));
        az = fmaf(az, s, fmaf(p0, c0.ps.z, p1 * c1.ps.z));
        aw = fmaf(aw, s, fmaf(p0, c0.ps.w, p1 * c1.ps.w));
        m = mnew;
    }
    if (j < end) {
        float2 er0 = g_edge_s[j];
        EdgeCalc c0 = edge_calc(er0, p4, pd, a4, web, lane);
        float mnew = fmaxf(m, c0.logit);
        float s = __expf(m - mnew);
        float p0 = __expf(c0.logit - mnew);
        den = fmaf(den, s, p0);
        ax = fmaf(ax, s, p0 * c0.ps.x);
        ay = fmaf(ay, s, p0 * c0.ps.y);
        az = fmaf(az, s, p0 * c0.ps.z);
        aw = fmaf(aw, s, p0 * c0.ps.w);
        m = mnew;
    }

    float inv = 1.0f / fmaxf(den, 1e-12f);
    float4* o4 = (float4*)out;
    float4 r = o4[d * 32 + lane];
    r.x = fmaf(ax, inv, r.x);
    r.y = fmaf(ay, inv, r.y);
    r.z = fmaf(az, inv, r.z);
    r.w = fmaf(aw, inv, r.w);
    o4[d * 32 + lane] = r;
}

// ================================================================================
extern "C" void kernel_launch(void* const* d_in, const int* in_sizes, int n_in,
                              void* d_out, int out_size)
{
    const float* x     = (const float*)d_in[0];
    const void*  ei    = (const void*)d_in[1];
    const float* ea    = (const float*)d_in[2];
    const float* W_lin = (const float*)d_in[3];
    const float* att   = (const float*)d_in[4];
    const float* W_eb  = (const float*)d_in[5];
    const float* bias  = (const float*)d_in[6];
    const float* W_res = (const float*)d_in[7];
    float* out = (float*)d_out;

    int N  = in_sizes[0] / 128;
    int E  = in_sizes[1] / 2;
    int Et = E + N;
    int nb = (N + 1023) / 1024;

    cudaFuncSetAttribute(mma_gemm_kernel,
                         cudaFuncAttributeMaxDynamicSharedMemorySize, GSM_TOTAL);

    int probe = (E < 65536) ? E : 65536;
    int initThreads = (N + 4 > probe) ? (N + 4) : probe;
    initdetect_kernel<<<(initThreads + 255) / 256, 256>>>((const long long*)ei, probe, N);

    prep_kernel<<<(N * 128 / 4 + 255) / 256, 256>>>(x, W_lin, W_res, N * 128);

    hist_kernel<<<(Et + 255) / 256, 256>>>(ei, E, N);
    scan1_kernel<<<nb, 1024>>>(N);
    scan2_kernel<<<1, 1024>>>(nb);
    scan3_kernel<<<nb, 1024>>>(N);
    scatter_kernel<<<(Et + 255) / 256, 256>>>(ei, ea, E, N);

    mma_gemm_kernel<<<dim3((N + 127) / 128, 2), 256, GSM_TOTAL>>>(bias, out, N);

    gat_node_kernel<<<(N * 32 + 255) / 256, 256>>>(att, W_eb, out, N);
}

// round 7
// speedup vs baseline: 1.5714x; 1.0684x over previous
#include <cuda_runtime.h>
#include <cuda_bf16.h>
#include <cstdint>

// ---------------------------------------------------------------------------
// SparseGATv2Layer: HMMA split-bf16 GEMM + edge-sorted online-softmax GAT.
// Two independent chains overlapped via graph-capturable fork-join streams:
//   chain A (capture stream): initdetect -> hist -> scan x3 -> scatter
//   chain B (side stream)   : prep -> mma_gemm
//   join                    : gat_node (one warp per dst, online softmax)
// ---------------------------------------------------------------------------

#define MAXN 50000
#define MAXE 800000
#define MAXET (MAXE + MAXN)

__device__ float    g_proj[MAXN * 128];
__device__ float2   g_edge_s[MAXET];
__device__ unsigned g_cnt[MAXN + 4];
__device__ unsigned g_tmp[MAXN];
__device__ unsigned g_bsum[1024];
__device__ unsigned g_off[MAXN + 1];
__device__ unsigned g_cur[MAXN];
__device__ int      g_idx64;

__device__ __align__(16) __nv_bfloat16 g_xh[MAXN * 128];
__device__ __align__(16) __nv_bfloat16 g_xl[MAXN * 128];
__device__ __align__(16) __nv_bfloat16 g_wh[256 * 128];
__device__ __align__(16) __nv_bfloat16 g_wl[256 * 128];

__device__ __forceinline__ uint32_t smem_to_u32(const void* p) {
    uint32_t a;
    asm("{ .reg .u64 t; cvta.to.shared.u64 t, %1; cvt.u32.u64 %0, t; }"
        : "=r"(a) : "l"(p));
    return a;
}

#define SWZ128(o) ((o) ^ (((o) >> 3) & 0x70))

#define LDSM_X4(r0, r1, r2, r3, addr) \
    asm volatile("ldmatrix.sync.aligned.m8n8.x4.shared.b16 {%0,%1,%2,%3}, [%4];" \
                 : "=r"(r0), "=r"(r1), "=r"(r2), "=r"(r3) : "r"(addr))

#define MMA16816(c, a, b) \
    asm volatile("mma.sync.aligned.m16n8k16.row.col.f32.bf16.bf16.f32 " \
                 "{%0,%1,%2,%3}, {%4,%5,%6,%7}, {%8,%9}, {%0,%1,%2,%3};" \
                 : "+f"((c)[0]), "+f"((c)[1]), "+f"((c)[2]), "+f"((c)[3]) \
                 : "r"((a)[0]), "r"((a)[1]), "r"((a)[2]), "r"((a)[3]), \
                   "r"((b)[0]), "r"((b)[1]))

// ---- edge-index accessor: int64 or int32, probed on device --------------------
__device__ __forceinline__ int load_idx(const void* ei, int i) {
    if (g_idx64)
        return (int)((const long long*)ei)[i];
    else
        return ((const int*)ei)[i];
}

// ================================================================================
// A1: zero histogram + dtype probe
// ================================================================================
__global__ void initdetect_kernel(const long long* ei, int probe, int N) {
    int i = blockIdx.x * blockDim.x + threadIdx.x;
    if (i == 0) { g_idx64 = 1; g_off[0] = 0; g_cur[0] = 0; }
    if (i < N + 4) g_cnt[i] = 0u;
    if (i < probe) {
        long long v = ei[i];
        if (v < 0 || v >= (long long)N) g_idx64 = 0;
    }
}

// ================================================================================
// B1: bf16 hi/lo split of x and concatenated weights [W_lin ; W_res]
// ================================================================================
__global__ void prep_kernel(const float* __restrict__ x,
                            const float* __restrict__ W_lin,
                            const float* __restrict__ W_res, int n) {
    int i = blockIdx.x * blockDim.x + threadIdx.x;
    int i4 = i * 4;
    if (i4 < n) {
        float4 v = *(const float4*)&x[i4];
        __nv_bfloat16 hx = __float2bfloat16(v.x), hy = __float2bfloat16(v.y);
        __nv_bfloat16 hz = __float2bfloat16(v.z), hw = __float2bfloat16(v.w);
        __nv_bfloat162 h01; h01.x = hx; h01.y = hy;
        __nv_bfloat162 h23; h23.x = hz; h23.y = hw;
        ((__nv_bfloat162*)g_xh)[i * 2]     = h01;
        ((__nv_bfloat162*)g_xh)[i * 2 + 1] = h23;
        __nv_bfloat162 l01, l23;
        l01.x = __float2bfloat16(v.x - __bfloat162float(hx));
        l01.y = __float2bfloat16(v.y - __bfloat162float(hy));
        l23.x = __float2bfloat16(v.z - __bfloat162float(hz));
        l23.y = __float2bfloat16(v.w - __bfloat162float(hw));
        ((__nv_bfloat162*)g_xl)[i * 2]     = l01;
        ((__nv_bfloat162*)g_xl)[i * 2 + 1] = l23;
    }
    if (i < 8192) {
        int j4 = i * 4;
        const float* Wsrc = (j4 < 16384) ? &W_lin[j4] : &W_res[j4 - 16384];
        float4 w = *(const float4*)Wsrc;
        __nv_bfloat16 hx = __float2bfloat16(w.x), hy = __float2bfloat16(w.y);
        __nv_bfloat16 hz = __float2bfloat16(w.z), hw = __float2bfloat16(w.w);
        __nv_bfloat162 h01; h01.x = hx; h01.y = hy;
        __nv_bfloat162 h23; h23.x = hz; h23.y = hw;
        ((__nv_bfloat162*)g_wh)[i * 2]     = h01;
        ((__nv_bfloat162*)g_wh)[i * 2 + 1] = h23;
        __nv_bfloat162 l01, l23;
        l01.x = __float2bfloat16(w.x - __bfloat162float(hx));
        l01.y = __float2bfloat16(w.y - __bfloat162float(hy));
        l23.x = __float2bfloat16(w.z - __bfloat162float(hz));
        l23.y = __float2bfloat16(w.w - __bfloat162float(hw));
        ((__nv_bfloat162*)g_wl)[i * 2]     = l01;
        ((__nv_bfloat162*)g_wl)[i * 2 + 1] = l23;
    }
}

// ================================================================================
// A2: histogram of dst
// ================================================================================
__global__ void hist_kernel(const void* __restrict__ ei, int E, int N) {
    int i = blockIdx.x * blockDim.x + threadIdx.x;
    int Et = E + N;
    if (i >= Et) return;
    int dst = (i < E) ? load_idx(ei, E + i) : (i - E);
    atomicAdd(&g_cnt[dst], 1u);
}

// ---- A3-A5: 3-kernel warp-shuffle scan -----------------------------------------
__device__ __forceinline__ unsigned warp_incl_scan(unsigned v, int lane) {
#pragma unroll
    for (int d = 1; d < 32; d <<= 1) {
        unsigned t = __shfl_up_sync(0xffffffffu, v, d);
        if (lane >= d) v += t;
    }
    return v;
}

__global__ void scan1_kernel(int N) {
    __shared__ unsigned wsum[32];
    int i = blockIdx.x * 1024 + threadIdx.x;
    int lane = threadIdx.x & 31;
    int wid = threadIdx.x >> 5;
    unsigned v = (i < N) ? g_cnt[i] : 0u;
    unsigned incl = warp_incl_scan(v, lane);
    if (lane == 31) wsum[wid] = incl;
    __syncthreads();
    if (wid == 0) {
        unsigned w = wsum[lane];
        wsum[lane] = warp_incl_scan(w, lane) - w;
    }
    __syncthreads();
    incl += wsum[wid];
    if (i < N) g_tmp[i] = incl;
    if (threadIdx.x == 1023) g_bsum[blockIdx.x] = incl;
}

__global__ void scan2_kernel(int nb) {
    __shared__ unsigned wsum[32];
    int lane = threadIdx.x & 31;
    int wid = threadIdx.x >> 5;
    unsigned v = (threadIdx.x < nb) ? g_bsum[threadIdx.x] : 0u;
    unsigned incl = warp_incl_scan(v, lane);
    if (lane == 31) wsum[wid] = incl;
    __syncthreads();
    if (wid == 0) {
        unsigned w = wsum[lane];
        wsum[lane] = warp_incl_scan(w, lane) - w;
    }
    __syncthreads();
    incl += wsum[wid];
    if (threadIdx.x < nb) g_bsum[threadIdx.x] = incl - v;
}

__global__ void scan3_kernel(int N) {
    int i = blockIdx.x * 1024 + threadIdx.x;
    if (i >= N) return;
    unsigned incl = g_tmp[i] + g_bsum[blockIdx.x];
    g_off[i + 1] = incl;
    if (i + 1 < N) g_cur[i + 1] = incl;
}

// ================================================================================
// A6: counting-sort scatter
// ================================================================================
__global__ void scatter_kernel(const void* __restrict__ ei,
                               const float* __restrict__ ea, int E, int N) {
    int i = blockIdx.x * blockDim.x + threadIdx.x;
    int Et = E + N;
    if (i >= Et) return;
    int src, dst; float red;
    if (i < E) {
        src = load_idx(ei, i);
        dst = load_idx(ei, E + i);
        float2 e2 = ((const float2*)ea)[i];
        red = e2.x + 0.35f * e2.y;
    } else {
        src = dst = i - E;
        red = 1.0f;
    }
    unsigned pos = atomicAdd(&g_cur[dst], 1u);
    g_edge_s[pos] = make_float2(__int_as_float(src), red);
}

// ================================================================================
// B2: HMMA split-bf16 GEMM. CTA = 128 rows x 128 cols; grid.y picks W half.
// D = Ah*Bh + Al*Bh + Ah*Bl, fp32 accumulate.
// ================================================================================
#define SA_HI 0
#define SA_LO 32768
#define SB_HI 65536
#define SB_LO 98304
#define GSM_TOTAL 131072

__global__ __launch_bounds__(256, 1) void mma_gemm_kernel(
    const float* __restrict__ bias, float* __restrict__ out, int N)
{
    extern __shared__ char smem[];
    const uint32_t sbase = smem_to_u32(smem);
    const int tid = threadIdx.x;
    const int lane = tid & 31;
    const int wid = tid >> 5;
    const int warpm = wid & 3;
    const int warpn = wid >> 2;
    const int rbase = blockIdx.x * 128;
    const int ybase = blockIdx.y * 128;

    const uint4* xh4 = (const uint4*)g_xh;
    const uint4* xl4 = (const uint4*)g_xl;
    const uint4* wh4 = (const uint4*)g_wh;
    const uint4* wl4 = (const uint4*)g_wl;
    const uint4 zero4 = make_uint4(0u, 0u, 0u, 0u);

#pragma unroll
    for (int idx = tid; idx < 128 * 16; idx += 256) {
        int r = idx >> 4;
        int u = idx & 15;
        int b = u >> 3;
        int u8 = u & 7;
        uint32_t off = (uint32_t)(b * 16384) + SWZ128((uint32_t)(r * 128 + u8 * 16));
        int arow = rbase + r;
        int agi = arow * 16 + u;
        bool ok = (arow < N);
        *(uint4*)(smem + SA_HI + off) = ok ? xh4[agi] : zero4;
        *(uint4*)(smem + SA_LO + off) = ok ? xl4[agi] : zero4;
        int wgi = (ybase + r) * 16 + u;
        *(uint4*)(smem + SB_HI + off) = wh4[wgi];
        *(uint4*)(smem + SB_LO + off) = wl4[wgi];
    }
    __syncthreads();

    float acc[2][8][4];
#pragma unroll
    for (int mt = 0; mt < 2; mt++)
#pragma unroll
        for (int nt = 0; nt < 8; nt++)
#pragma unroll
            for (int q = 0; q < 4; q++) acc[mt][nt][q] = 0.0f;

    const int a_row_off = lane & 15;
    const int a_seg = (lane >> 4) & 1;
    const int b_row_off = (lane & 7) + ((lane >> 4) & 1) * 8;
    const int b_seg = (lane >> 3) & 1;

#pragma unroll
    for (int b = 0; b < 2; b++) {
        const uint32_t ahb = sbase + SA_HI + b * 16384;
        const uint32_t alb = sbase + SA_LO + b * 16384;
        const uint32_t bhb = sbase + SB_HI + b * 16384;
        const uint32_t blb = sbase + SB_LO + b * 16384;
#pragma unroll
        for (int s = 0; s < 4; s++) {
            const int c0 = s * 16;
            uint32_t ah[8], al[8];
#pragma unroll
            for (int mt = 0; mt < 2; mt++) {
                int row = warpm * 32 + mt * 16 + a_row_off;
                uint32_t off = SWZ128((uint32_t)(row * 128 + (c0 + a_seg * 8) * 2));
                LDSM_X4(ah[mt*4], ah[mt*4+1], ah[mt*4+2], ah[mt*4+3], ahb + off);
                LDSM_X4(al[mt*4], al[mt*4+1], al[mt*4+2], al[mt*4+3], alb + off);
            }
            uint32_t bf[16];
#pragma unroll
            for (int p = 0; p < 4; p++) {
                int row = warpn * 64 + p * 16 + b_row_off;
                uint32_t off = SWZ128((uint32_t)(row * 128 + (c0 + b_seg * 8) * 2));
                LDSM_X4(bf[p*4], bf[p*4+1], bf[p*4+2], bf[p*4+3], bhb + off);
            }
#pragma unroll
            for (int mt = 0; mt < 2; mt++)
#pragma unroll
                for (int nt = 0; nt < 8; nt++) {
                    uint32_t* bb = &bf[(nt >> 1) * 4 + (nt & 1) * 2];
                    MMA16816(acc[mt][nt], &ah[mt*4], bb);   // hh
                    MMA16816(acc[mt][nt], &al[mt*4], bb);   // lh
                }
#pragma unroll
            for (int p = 0; p < 4; p++) {
                int row = warpn * 64 + p * 16 + b_row_off;
                uint32_t off = SWZ128((uint32_t)(row * 128 + (c0 + b_seg * 8) * 2));
                LDSM_X4(bf[p*4], bf[p*4+1], bf[p*4+2], bf[p*4+3], blb + off);
            }
#pragma unroll
            for (int mt = 0; mt < 2; mt++)
#pragma unroll
                for (int nt = 0; nt < 8; nt++) {
                    uint32_t* bb = &bf[(nt >> 1) * 4 + (nt & 1) * 2];
                    MMA16816(acc[mt][nt], &ah[mt*4], bb);   // hl
                }
        }
    }

    const int rr = lane >> 2;
    const int cc = (lane & 3) * 2;
#pragma unroll
    for (int mt = 0; mt < 2; mt++) {
        int row0 = rbase + warpm * 32 + mt * 16 + rr;
#pragma unroll
        for (int nt = 0; nt < 8; nt++) {
            int col = warpn * 64 + nt * 8 + cc;
            if (blockIdx.y == 0) {
                if (row0 < N)
                    *(float2*)&g_proj[row0 * 128 + col] =
                        make_float2(acc[mt][nt][0], acc[mt][nt][1]);
                if (row0 + 8 < N)
                    *(float2*)&g_proj[(row0 + 8) * 128 + col] =
                        make_float2(acc[mt][nt][2], acc[mt][nt][3]);
            } else {
                float2 bb = *(const float2*)&bias[col];
                if (row0 < N)
                    *(float2*)&out[row0 * 128 + col] =
                        make_float2(acc[mt][nt][0] + bb.x, acc[mt][nt][1] + bb.y);
                if (row0 + 8 < N)
                    *(float2*)&out[(row0 + 8) * 128 + col] =
                        make_float2(acc[mt][nt][2] + bb.x, acc[mt][nt][3] + bb.y);
            }
        }
    }
}

// ================================================================================
// J1: GAT node kernel, single pass with online softmax
// ================================================================================
struct EdgeCalc { float4 ps; float logit; };

__device__ __forceinline__ EdgeCalc edge_calc(float2 er, const float4* p4,
                                              float4 pd, float4 a4, float web,
                                              int lane)
{
    EdgeCalc r;
    int src = __float_as_int(er.x);
    r.ps = p4[src * 32 + lane];
    float zx = r.ps.x + pd.x; zx = fmaxf(zx, 0.2f * zx);
    float zy = r.ps.y + pd.y; zy = fmaxf(zy, 0.2f * zy);
    float zz = r.ps.z + pd.z; zz = fmaxf(zz, 0.2f * zz);
    float zw = r.ps.w + pd.w; zw = fmaxf(zw, 0.2f * zw);
    float part = zx * a4.x + zy * a4.y + zz * a4.z + zw * a4.w;
    part += __shfl_xor_sync(0xffffffffu, part, 4);
    part += __shfl_xor_sync(0xffffffffu, part, 2);
    part += __shfl_xor_sync(0xffffffffu, part, 1);
    r.logit = fmaf(er.y, web, part);
    return r;
}

__global__ __launch_bounds__(256) void gat_node_kernel(
    const float* __restrict__ att, const float* __restrict__ W_eb,
    float* __restrict__ out, int N)
{
    int warp = (blockIdx.x * blockDim.x + threadIdx.x) >> 5;
    int lane = threadIdx.x & 31;
    if (warp >= N) return;
    const int d = warp;
    const int h = lane >> 3;

    const int beg = (int)g_off[d];
    const int end = (int)g_off[d + 1];

    const float4* p4 = (const float4*)g_proj;
    float4 pd = p4[d * 32 + lane];
    float4 a4 = ((const float4*)att)[lane];
    float web = __ldg(&W_eb[h]);

    float m = -3.4e38f, den = 0.0f;
    float ax = 0.0f, ay = 0.0f, az = 0.0f, aw = 0.0f;

    int j = beg;
    for (; j + 1 < end; j += 2) {
        float2 er0 = g_edge_s[j];
        float2 er1 = g_edge_s[j + 1];
        EdgeCalc c0 = edge_calc(er0, p4, pd, a4, web, lane);
        EdgeCalc c1 = edge_calc(er1, p4, pd, a4, web, lane);

        float mnew = fmaxf(m, fmaxf(c0.logit, c1.logit));
        float s  = __expf(m - mnew);
        float p0 = __expf(c0.logit - mnew);
        float p1 = __expf(c1.logit - mnew);
        den = fmaf(den, s, p0 + p1);
        ax = fmaf(ax, s, fmaf(p0, c0.ps.x, p1 * c1.ps.x));
        ay = fmaf(ay, s, fmaf(p0, c0.ps.y, p1 * c1.ps.y));
        az = fmaf(az, s, fmaf(p0, c0.ps.z, p1 * c1.ps.z));
        aw = fmaf(aw, s, fmaf(p0, c0.ps.w, p1 * c1.ps.w));
        m = mnew;
    }
    if (j < end) {
        float2 er0 = g_edge_s[j];
        EdgeCalc c0 = edge_calc(er0, p4, pd, a4, web, lane);
        float mnew = fmaxf(m, c0.logit);
        float s = __expf(m - mnew);
        float p0 = __expf(c0.logit - mnew);
        den = fmaf(den, s, p0);
        ax = fmaf(ax, s, p0 * c0.ps.x);
        ay = fmaf(ay, s, p0 * c0.ps.y);
        az = fmaf(az, s, p0 * c0.ps.z);
        aw = fmaf(aw, s, p0 * c0.ps.w);
        m = mnew;
    }

    float inv = 1.0f / fmaxf(den, 1e-12f);
    float4* o4 = (float4*)out;
    float4 r = o4[d * 32 + lane];
    r.x = fmaf(ax, inv, r.x);
    r.y = fmaf(ay, inv, r.y);
    r.z = fmaf(az, inv, r.z);
    r.w = fmaf(aw, inv, r.w);
    o4[d * 32 + lane] = r;
}

// ================================================================================
extern "C" void kernel_launch(void* const* d_in, const int* in_sizes, int n_in,
                              void* d_out, int out_size)
{
    const float* x     = (const float*)d_in[0];
    const void*  ei    = (const void*)d_in[1];
    const float* ea    = (const float*)d_in[2];
    const float* W_lin = (const float*)d_in[3];
    const float* att   = (const float*)d_in[4];
    const float* W_eb  = (const float*)d_in[5];
    const float* bias  = (const float*)d_in[6];
    const float* W_res = (const float*)d_in[7];
    float* out = (float*)d_out;

    int N  = in_sizes[0] / 128;
    int E  = in_sizes[1] / 2;
    int Et = E + N;
    int nb = (N + 1023) / 1024;

    // one-time host-side resources (no device memory involved)
    static cudaStream_t s_gemm = nullptr;
    static cudaEvent_t ev_fork = nullptr, ev_join = nullptr;
    if (s_gemm == nullptr) {
        cudaStreamCreateWithFlags(&s_gemm, cudaStreamNonBlocking);
        cudaEventCreateWithFlags(&ev_fork, cudaEventDisableTiming);
        cudaEventCreateWithFlags(&ev_join, cudaEventDisableTiming);
        cudaFuncSetAttribute(mma_gemm_kernel,
                             cudaFuncAttributeMaxDynamicSharedMemorySize, GSM_TOTAL);
    }

    // ---- fork: GEMM chain on side stream ----
    cudaEventRecord(ev_fork, 0);
    cudaStreamWaitEvent(s_gemm, ev_fork, 0);

    prep_kernel<<<(N * 128 / 4 + 255) / 256, 256, 0, s_gemm>>>(x, W_lin, W_res, N * 128);
    mma_gemm_kernel<<<dim3((N + 127) / 128, 2), 256, GSM_TOTAL, s_gemm>>>(bias, out, N);
    cudaEventRecord(ev_join, s_gemm);

    // ---- edge chain on capture stream ----
    int probe = (E < 65536) ? E : 65536;
    int initThreads = (N + 4 > probe) ? (N + 4) : probe;
    initdetect_kernel<<<(initThreads + 255) / 256, 256>>>((const long long*)ei, probe, N);
    hist_kernel<<<(Et + 255) / 256, 256>>>(ei, E, N);
    scan1_kernel<<<nb, 1024>>>(N);
    scan2_kernel<<<1, 1024>>>(nb);
    scan3_kernel<<<nb, 1024>>>(N);
    scatter_kernel<<<(Et + 255) / 256, 256>>>(ei, ea, E, N);

    // ---- join, then node kernel ----
    cudaStreamWaitEvent(0, ev_join, 0);
    gat_node_kernel<<<(N * 32 + 255) / 256, 256>>>(att, W_eb, out, N);
}

// round 8
// speedup vs baseline: 1.6059x; 1.0220x over previous
#include <cuda_runtime.h>
#include <cuda_bf16.h>
#include <cstdint>

// ---------------------------------------------------------------------------
// SparseGATv2Layer: HMMA split-bf16 GEMM + edge-sorted online-softmax GAT.
// Fork-join streams:
//   chain A (capture stream): initdetect -> hist -> scan x3 -> scatter
//   chain B (side stream)   : prep -> mma_gemm
//   join                    : gat_node (one warp per dst, online softmax, MLP=4)
// ---------------------------------------------------------------------------

#define MAXN 50000
#define MAXE 800000
#define MAXET (MAXE + MAXN)

__device__ float    g_proj[MAXN * 128];
__device__ float2   g_edge_s[MAXET];
__device__ unsigned g_cnt[MAXN + 4];
__device__ unsigned g_tmp[MAXN];
__device__ unsigned g_bsum[1024];
__device__ unsigned g_off[MAXN + 1];
__device__ unsigned g_cur[MAXN];
__device__ int      g_idx64;

__device__ __align__(16) __nv_bfloat16 g_xh[MAXN * 128];
__device__ __align__(16) __nv_bfloat16 g_xl[MAXN * 128];
__device__ __align__(16) __nv_bfloat16 g_wh[256 * 128];
__device__ __align__(16) __nv_bfloat16 g_wl[256 * 128];

__device__ __forceinline__ uint32_t smem_to_u32(const void* p) {
    uint32_t a;
    asm("{ .reg .u64 t; cvta.to.shared.u64 t, %1; cvt.u32.u64 %0, t; }"
        : "=r"(a) : "l"(p));
    return a;
}

#define SWZ128(o) ((o) ^ (((o) >> 3) & 0x70))

#define LDSM_X4(r0, r1, r2, r3, addr) \
    asm volatile("ldmatrix.sync.aligned.m8n8.x4.shared.b16 {%0,%1,%2,%3}, [%4];" \
                 : "=r"(r0), "=r"(r1), "=r"(r2), "=r"(r3) : "r"(addr))

#define MMA16816(c, a, b) \
    asm volatile("mma.sync.aligned.m16n8k16.row.col.f32.bf16.bf16.f32 " \
                 "{%0,%1,%2,%3}, {%4,%5,%6,%7}, {%8,%9}, {%0,%1,%2,%3};" \
                 : "+f"((c)[0]), "+f"((c)[1]), "+f"((c)[2]), "+f"((c)[3]) \
                 : "r"((a)[0]), "r"((a)[1]), "r"((a)[2]), "r"((a)[3]), \
                   "r"((b)[0]), "r"((b)[1]))

// ---- edge-index accessor: int64 or int32, probed on device --------------------
__device__ __forceinline__ int load_idx(const void* ei, int i) {
    if (g_idx64)
        return (int)((const long long*)ei)[i];
    else
        return ((const int*)ei)[i];
}

// ================================================================================
// A1: zero histogram + dtype probe
// ================================================================================
__global__ void initdetect_kernel(const long long* ei, int probe, int N) {
    int i = blockIdx.x * blockDim.x + threadIdx.x;
    if (i == 0) { g_idx64 = 1; g_off[0] = 0; g_cur[0] = 0; }
    if (i < N + 4) g_cnt[i] = 0u;
    if (i < probe) {
        long long v = ei[i];
        if (v < 0 || v >= (long long)N) g_idx64 = 0;
    }
}

// ================================================================================
// B1: bf16 hi/lo split of x and concatenated weights [W_lin ; W_res]
// ================================================================================
__global__ void prep_kernel(const float* __restrict__ x,
                            const float* __restrict__ W_lin,
                            const float* __restrict__ W_res, int n) {
    int i = blockIdx.x * blockDim.x + threadIdx.x;
    int i4 = i * 4;
    if (i4 < n) {
        float4 v = *(const float4*)&x[i4];
        __nv_bfloat16 hx = __float2bfloat16(v.x), hy = __float2bfloat16(v.y);
        __nv_bfloat16 hz = __float2bfloat16(v.z), hw = __float2bfloat16(v.w);
        __nv_bfloat162 h01; h01.x = hx; h01.y = hy;
        __nv_bfloat162 h23; h23.x = hz; h23.y = hw;
        ((__nv_bfloat162*)g_xh)[i * 2]     = h01;
        ((__nv_bfloat162*)g_xh)[i * 2 + 1] = h23;
        __nv_bfloat162 l01, l23;
        l01.x = __float2bfloat16(v.x - __bfloat162float(hx));
        l01.y = __float2bfloat16(v.y - __bfloat162float(hy));
        l23.x = __float2bfloat16(v.z - __bfloat162float(hz));
        l23.y = __float2bfloat16(v.w - __bfloat162float(hw));
        ((__nv_bfloat162*)g_xl)[i * 2]     = l01;
        ((__nv_bfloat162*)g_xl)[i * 2 + 1] = l23;
    }
    if (i < 8192) {
        int j4 = i * 4;
        const float* Wsrc = (j4 < 16384) ? &W_lin[j4] : &W_res[j4 - 16384];
        float4 w = *(const float4*)Wsrc;
        __nv_bfloat16 hx = __float2bfloat16(w.x), hy = __float2bfloat16(w.y);
        __nv_bfloat16 hz = __float2bfloat16(w.z), hw = __float2bfloat16(w.w);
        __nv_bfloat162 h01; h01.x = hx; h01.y = hy;
        __nv_bfloat162 h23; h23.x = hz; h23.y = hw;
        ((__nv_bfloat162*)g_wh)[i * 2]     = h01;
        ((__nv_bfloat162*)g_wh)[i * 2 + 1] = h23;
        __nv_bfloat162 l01, l23;
        l01.x = __float2bfloat16(w.x - __bfloat162float(hx));
        l01.y = __float2bfloat16(w.y - __bfloat162float(hy));
        l23.x = __float2bfloat16(w.z - __bfloat162float(hz));
        l23.y = __float2bfloat16(w.w - __bfloat162float(hw));
        ((__nv_bfloat162*)g_wl)[i * 2]     = l01;
        ((__nv_bfloat162*)g_wl)[i * 2 + 1] = l23;
    }
}

// ================================================================================
// A2: histogram of dst, 4 edges per thread (independent loads + atomics)
// ================================================================================
__global__ void hist_kernel(const void* __restrict__ ei, int E, int N) {
    int base = (blockIdx.x * blockDim.x + threadIdx.x) * 4;
    int Et = E + N;
    if (base >= Et) return;
    int d0 = -1, d1 = -1, d2 = -1, d3 = -1;
    d0 = (base < E) ? load_idx(ei, E + base) : (base - E);
    if (base + 1 < Et) d1 = (base + 1 < E) ? load_idx(ei, E + base + 1) : (base + 1 - E);
    if (base + 2 < Et) d2 = (base + 2 < E) ? load_idx(ei, E + base + 2) : (base + 2 - E);
    if (base + 3 < Et) d3 = (base + 3 < E) ? load_idx(ei, E + base + 3) : (base + 3 - E);
    atomicAdd(&g_cnt[d0], 1u);
    if (d1 >= 0) atomicAdd(&g_cnt[d1], 1u);
    if (d2 >= 0) atomicAdd(&g_cnt[d2], 1u);
    if (d3 >= 0) atomicAdd(&g_cnt[d3], 1u);
}

// ---- A3-A5: 3-kernel warp-shuffle scan -----------------------------------------
__device__ __forceinline__ unsigned warp_incl_scan(unsigned v, int lane) {
#pragma unroll
    for (int d = 1; d < 32; d <<= 1) {
        unsigned t = __shfl_up_sync(0xffffffffu, v, d);
        if (lane >= d) v += t;
    }
    return v;
}

__global__ void scan1_kernel(int N) {
    __shared__ unsigned wsum[32];
    int i = blockIdx.x * 1024 + threadIdx.x;
    int lane = threadIdx.x & 31;
    int wid = threadIdx.x >> 5;
    unsigned v = (i < N) ? g_cnt[i] : 0u;
    unsigned incl = warp_incl_scan(v, lane);
    if (lane == 31) wsum[wid] = incl;
    __syncthreads();
    if (wid == 0) {
        unsigned w = wsum[lane];
        wsum[lane] = warp_incl_scan(w, lane) - w;
    }
    __syncthreads();
    incl += wsum[wid];
    if (i < N) g_tmp[i] = incl;
    if (threadIdx.x == 1023) g_bsum[blockIdx.x] = incl;
}

__global__ void scan2_kernel(int nb) {
    __shared__ unsigned wsum[32];
    int lane = threadIdx.x & 31;
    int wid = threadIdx.x >> 5;
    unsigned v = (threadIdx.x < nb) ? g_bsum[threadIdx.x] : 0u;
    unsigned incl = warp_incl_scan(v, lane);
    if (lane == 31) wsum[wid] = incl;
    __syncthreads();
    if (wid == 0) {
        unsigned w = wsum[lane];
        wsum[lane] = warp_incl_scan(w, lane) - w;
    }
    __syncthreads();
    incl += wsum[wid];
    if (threadIdx.x < nb) g_bsum[threadIdx.x] = incl - v;
}

__global__ void scan3_kernel(int N) {
    int i = blockIdx.x * 1024 + threadIdx.x;
    if (i >= N) return;
    unsigned incl = g_tmp[i] + g_bsum[blockIdx.x];
    g_off[i + 1] = incl;
    if (i + 1 < N) g_cur[i + 1] = incl;
}

// ================================================================================
// A6: counting-sort scatter, 2 edges per thread
// ================================================================================
__global__ void scatter_kernel(const void* __restrict__ ei,
                               const float* __restrict__ ea, int E, int N) {
    int base = (blockIdx.x * blockDim.x + threadIdx.x) * 2;
    int Et = E + N;
    if (base >= Et) return;
#pragma unroll
    for (int q = 0; q < 2; q++) {
        int i = base + q;
        if (i >= Et) break;
        int src, dst; float red;
        if (i < E) {
            src = load_idx(ei, i);
            dst = load_idx(ei, E + i);
            float2 e2 = ((const float2*)ea)[i];
            red = e2.x + 0.35f * e2.y;
        } else {
            src = dst = i - E;
            red = 1.0f;
        }
        unsigned pos = atomicAdd(&g_cur[dst], 1u);
        g_edge_s[pos] = make_float2(__int_as_float(src), red);
    }
}

// ================================================================================
// B2: HMMA split-bf16 GEMM. CTA = 128 rows x 128 cols; grid.y picks W half.
// ================================================================================
#define SA_HI 0
#define SA_LO 32768
#define SB_HI 65536
#define SB_LO 98304
#define GSM_TOTAL 131072

__global__ __launch_bounds__(256, 1) void mma_gemm_kernel(
    const float* __restrict__ bias, float* __restrict__ out, int N)
{
    extern __shared__ char smem[];
    const uint32_t sbase = smem_to_u32(smem);
    const int tid = threadIdx.x;
    const int lane = tid & 31;
    const int wid = tid >> 5;
    const int warpm = wid & 3;
    const int warpn = wid >> 2;
    const int rbase = blockIdx.x * 128;
    const int ybase = blockIdx.y * 128;

    const uint4* xh4 = (const uint4*)g_xh;
    const uint4* xl4 = (const uint4*)g_xl;
    const uint4* wh4 = (const uint4*)g_wh;
    const uint4* wl4 = (const uint4*)g_wl;
    const uint4 zero4 = make_uint4(0u, 0u, 0u, 0u);

#pragma unroll
    for (int idx = tid; idx < 128 * 16; idx += 256) {
        int r = idx >> 4;
        int u = idx & 15;
        int b = u >> 3;
        int u8 = u & 7;
        uint32_t off = (uint32_t)(b * 16384) + SWZ128((uint32_t)(r * 128 + u8 * 16));
        int arow = rbase + r;
        int agi = arow * 16 + u;
        bool ok = (arow < N);
        *(uint4*)(smem + SA_HI + off) = ok ? xh4[agi] : zero4;
        *(uint4*)(smem + SA_LO + off) = ok ? xl4[agi] : zero4;
        int wgi = (ybase + r) * 16 + u;
        *(uint4*)(smem + SB_HI + off) = wh4[wgi];
        *(uint4*)(smem + SB_LO + off) = wl4[wgi];
    }
    __syncthreads();

    float acc[2][8][4];
#pragma unroll
    for (int mt = 0; mt < 2; mt++)
#pragma unroll
        for (int nt = 0; nt < 8; nt++)
#pragma unroll
            for (int q = 0; q < 4; q++) acc[mt][nt][q] = 0.0f;

    const int a_row_off = lane & 15;
    const int a_seg = (lane >> 4) & 1;
    const int b_row_off = (lane & 7) + ((lane >> 4) & 1) * 8;
    const int b_seg = (lane >> 3) & 1;

#pragma unroll
    for (int b = 0; b < 2; b++) {
        const uint32_t ahb = sbase + SA_HI + b * 16384;
        const uint32_t alb = sbase + SA_LO + b * 16384;
        const uint32_t bhb = sbase + SB_HI + b * 16384;
        const uint32_t blb = sbase + SB_LO + b * 16384;
#pragma unroll
        for (int s = 0; s < 4; s++) {
            const int c0 = s * 16;
            uint32_t ah[8], al[8];
#pragma unroll
            for (int mt = 0; mt < 2; mt++) {
                int row = warpm * 32 + mt * 16 + a_row_off;
                uint32_t off = SWZ128((uint32_t)(row * 128 + (c0 + a_seg * 8) * 2));
                LDSM_X4(ah[mt*4], ah[mt*4+1], ah[mt*4+2], ah[mt*4+3], ahb + off);
                LDSM_X4(al[mt*4], al[mt*4+1], al[mt*4+2], al[mt*4+3], alb + off);
            }
            uint32_t bf[16];
#pragma unroll
            for (int p = 0; p < 4; p++) {
                int row = warpn * 64 + p * 16 + b_row_off;
                uint32_t off = SWZ128((uint32_t)(row * 128 + (c0 + b_seg * 8) * 2));
                LDSM_X4(bf[p*4], bf[p*4+1], bf[p*4+2], bf[p*4+3], bhb + off);
            }
#pragma unroll
            for (int mt = 0; mt < 2; mt++)
#pragma unroll
                for (int nt = 0; nt < 8; nt++) {
                    uint32_t* bb = &bf[(nt >> 1) * 4 + (nt & 1) * 2];
                    MMA16816(acc[mt][nt], &ah[mt*4], bb);   // hh
                    MMA16816(acc[mt][nt], &al[mt*4], bb);   // lh
                }
#pragma unroll
            for (int p = 0; p < 4; p++) {
                int row = warpn * 64 + p * 16 + b_row_off;
                uint32_t off = SWZ128((uint32_t)(row * 128 + (c0 + b_seg * 8) * 2));
                LDSM_X4(bf[p*4], bf[p*4+1], bf[p*4+2], bf[p*4+3], blb + off);
            }
#pragma unroll
            for (int mt = 0; mt < 2; mt++)
#pragma unroll
                for (int nt = 0; nt < 8; nt++) {
                    uint32_t* bb = &bf[(nt >> 1) * 4 + (nt & 1) * 2];
                    MMA16816(acc[mt][nt], &ah[mt*4], bb);   // hl
                }
        }
    }

    const int rr = lane >> 2;
    const int cc = (lane & 3) * 2;
#pragma unroll
    for (int mt = 0; mt < 2; mt++) {
        int row0 = rbase + warpm * 32 + mt * 16 + rr;
#pragma unroll
        for (int nt = 0; nt < 8; nt++) {
            int col = warpn * 64 + nt * 8 + cc;
            if (blockIdx.y == 0) {
                if (row0 < N)
                    *(float2*)&g_proj[row0 * 128 + col] =
                        make_float2(acc[mt][nt][0], acc[mt][nt][1]);
                if (row0 + 8 < N)
                    *(float2*)&g_proj[(row0 + 8) * 128 + col] =
                        make_float2(acc[mt][nt][2], acc[mt][nt][3]);
            } else {
                float2 bb = *(const float2*)&bias[col];
                if (row0 < N)
                    *(float2*)&out[row0 * 128 + col] =
                        make_float2(acc[mt][nt][0] + bb.x, acc[mt][nt][1] + bb.y);
                if (row0 + 8 < N)
                    *(float2*)&out[(row0 + 8) * 128 + col] =
                        make_float2(acc[mt][nt][2] + bb.x, acc[mt][nt][3] + bb.y);
            }
        }
    }
}

// ================================================================================
// J1: GAT node kernel, single pass online softmax, unroll 4 (MLP=4 gathers)
// ================================================================================
struct EdgeCalc { float4 ps; float logit; };

__device__ __forceinline__ EdgeCalc edge_calc(float2 er, const float4* p4,
                                              float4 pd, float4 a4, float web,
                                              int lane)
{
    EdgeCalc r;
    int src = __float_as_int(er.x);
    r.ps = p4[src * 32 + lane];
    float zx = r.ps.x + pd.x; zx = fmaxf(zx, 0.2f * zx);
    float zy = r.ps.y + pd.y; zy = fmaxf(zy, 0.2f * zy);
    float zz = r.ps.z + pd.z; zz = fmaxf(zz, 0.2f * zz);
    float zw = r.ps.w + pd.w; zw = fmaxf(zw, 0.2f * zw);
    float part = zx * a4.x + zy * a4.y + zz * a4.z + zw * a4.w;
    part += __shfl_xor_sync(0xffffffffu, part, 4);
    part += __shfl_xor_sync(0xffffffffu, part, 2);
    part += __shfl_xor_sync(0xffffffffu, part, 1);
    r.logit = fmaf(er.y, web, part);
    return r;
}

__global__ __launch_bounds__(256) void gat_node_kernel(
    const float* __restrict__ att, const float* __restrict__ W_eb,
    float* __restrict__ out, int N)
{
    int warp = (blockIdx.x * blockDim.x + threadIdx.x) >> 5;
    int lane = threadIdx.x & 31;
    if (warp >= N) return;
    const int d = warp;
    const int h = lane >> 3;

    const int beg = (int)g_off[d];
    const int end = (int)g_off[d + 1];

    const float4* p4 = (const float4*)g_proj;
    float4 pd = p4[d * 32 + lane];
    float4 a4 = ((const float4*)att)[lane];
    float web = __ldg(&W_eb[h]);

    float m = -3.4e38f, den = 0.0f;
    float ax = 0.0f, ay = 0.0f, az = 0.0f, aw = 0.0f;

    int j = beg;
    // unroll 4: four independent gathers in flight
    for (; j + 3 < end; j += 4) {
        float2 er0 = g_edge_s[j];
        float2 er1 = g_edge_s[j + 1];
        float2 er2 = g_edge_s[j + 2];
        float2 er3 = g_edge_s[j + 3];
        EdgeCalc c0 = edge_calc(er0, p4, pd, a4, web, lane);
        EdgeCalc c1 = edge_calc(er1, p4, pd, a4, web, lane);
        EdgeCalc c2 = edge_calc(er2, p4, pd, a4, web, lane);
        EdgeCalc c3 = edge_calc(er3, p4, pd, a4, web, lane);

        float mnew = fmaxf(fmaxf(m, fmaxf(c0.logit, c1.logit)),
                           fmaxf(c2.logit, c3.logit));
        float s  = __expf(m - mnew);
        float p0 = __expf(c0.logit - mnew);
        float p1 = __expf(c1.logit - mnew);
        float p2 = __expf(c2.logit - mnew);
        float p3 = __expf(c3.logit - mnew);
        den = fmaf(den, s, (p0 + p1) + (p2 + p3));
        ax = fmaf(ax, s, fmaf(p0, c0.ps.x, p1 * c1.ps.x) + fmaf(p2, c2.ps.x, p3 * c3.ps.x));
        ay = fmaf(ay, s, fmaf(p0, c0.ps.y, p1 * c1.ps.y) + fmaf(p2, c2.ps.y, p3 * c3.ps.y));
        az = fmaf(az, s, fmaf(p0, c0.ps.z, p1 * c1.ps.z) + fmaf(p2, c2.ps.z, p3 * c3.ps.z));
        aw = fmaf(aw, s, fmaf(p0, c0.ps.w, p1 * c1.ps.w) + fmaf(p2, c2.ps.w, p3 * c3.ps.w));
        m = mnew;
    }
    for (; j < end; ++j) {
        float2 er0 = g_edge_s[j];
        EdgeCalc c0 = edge_calc(er0, p4, pd, a4, web, lane);
        float mnew = fmaxf(m, c0.logit);
        float s = __expf(m - mnew);
        float p0 = __expf(c0.logit - mnew);
        den = fmaf(den, s, p0);
        ax = fmaf(ax, s, p0 * c0.ps.x);
        ay = fmaf(ay, s, p0 * c0.ps.y);
        az = fmaf(az, s, p0 * c0.ps.z);
        aw = fmaf(aw, s, p0 * c0.ps.w);
        m = mnew;
    }

    float inv = 1.0f / fmaxf(den, 1e-12f);
    float4* o4 = (float4*)out;
    float4 r = o4[d * 32 + lane];
    r.x = fmaf(ax, inv, r.x);
    r.y = fmaf(ay, inv, r.y);
    r.z = fmaf(az, inv, r.z);
    r.w = fmaf(aw, inv, r.w);
    o4[d * 32 + lane] = r;
}

// ================================================================================
extern "C" void kernel_launch(void* const* d_in, const int* in_sizes, int n_in,
                              void* d_out, int out_size)
{
    const float* x     = (const float*)d_in[0];
    const void*  ei    = (const void*)d_in[1];
    const float* ea    = (const float*)d_in[2];
    const float* W_lin = (const float*)d_in[3];
    const float* att   = (const float*)d_in[4];
    const float* W_eb  = (const float*)d_in[5];
    const float* bias  = (const float*)d_in[6];
    const float* W_res = (const float*)d_in[7];
    float* out = (float*)d_out;

    int N  = in_sizes[0] / 128;
    int E  = in_sizes[1] / 2;
    int Et = E + N;
    int nb = (N + 1023) / 1024;

    static cudaStream_t s_gemm = nullptr;
    static cudaEvent_t ev_fork = nullptr, ev_join = nullptr;
    if (s_gemm == nullptr) {
        cudaStreamCreateWithFlags(&s_gemm, cudaStreamNonBlocking);
        cudaEventCreateWithFlags(&ev_fork, cudaEventDisableTiming);
        cudaEventCreateWithFlags(&ev_join, cudaEventDisableTiming);
        cudaFuncSetAttribute(mma_gemm_kernel,
                             cudaFuncAttributeMaxDynamicSharedMemorySize, GSM_TOTAL);
    }

    // ---- fork: GEMM chain on side stream ----
    cudaEventRecord(ev_fork, 0);
    cudaStreamWaitEvent(s_gemm, ev_fork, 0);

    prep_kernel<<<(N * 128 / 4 + 255) / 256, 256, 0, s_gemm>>>(x, W_lin, W_res, N * 128);
    mma_gemm_kernel<<<dim3((N + 127) / 128, 2), 256, GSM_TOTAL, s_gemm>>>(bias, out, N);
    cudaEventRecord(ev_join, s_gemm);

    // ---- edge chain on capture stream ----
    int probe = (E < 65536) ? E : 65536;
    int initThreads = (N + 4 > probe) ? (N + 4) : probe;
    initdetect_kernel<<<(initThreads + 255) / 256, 256>>>((const long long*)ei, probe, N);
    hist_kernel<<<(Et / 4 + 256) / 256, 256>>>(ei, E, N);
    scan1_kernel<<<nb, 1024>>>(N);
    scan2_kernel<<<1, 1024>>>(nb);
    scan3_kernel<<<nb, 1024>>>(N);
    scatter_kernel<<<(Et / 2 + 256) / 256, 256>>>(ei, ea, E, N);

    // ---- join, then node kernel ----
    cudaStreamWaitEvent(0, ev_join, 0);
    gat_node_kernel<<<(N * 32 + 255) / 256, 256>>>(att, W_eb, out, N);
}